// round 1
// baseline (speedup 1.0000x reference)
#include <cuda_runtime.h>
#include <cstdint>

// ---------------- problem constants ----------------
#define NP 100000
#define NL 80000
#define NG 50000
#define EDG 400000
#define DIN 512
#define DOUT 128
#define TOTROWS 690000   // sum over 9 relations of N[src] == sum of N[dst]

// per-relation metadata (host side)
static const int SRC_T[9] = {0,0,0,1,1,1,2,2,2};
static const int DST_T[9] = {0,1,2,1,0,2,2,0,1};
static const int NTY[3]   = {NP, NL, NG};
static const int SOFF[9]  = {0,100000,200000,300000,380000,460000,540000,590000,640000};
static const int DOFF[9]  = {0,100000,180000,230000,310000,410000,460000,510000,610000};
static const int OUTROW[3]= {0, NP, NP+NL};

// ---------------- device scratch (static, no allocation) ----------------
__device__ float    g_H[(size_t)TOTROWS * DOUT];   // projected src features per relation (353 MB)
__device__ float    g_ssrc[TOTROWS];               // <h_src, a_s> per (relation, src node)
__device__ float    g_sdst[TOTROWS];               // <h_dst, a_d> per (relation, dst node)
__device__ unsigned g_m[TOTROWS];                  // segment max (orderable-uint encoded)
__device__ float    g_den[TOTROWS];                // segment softmax denominator
__device__ float    g_e[9 * EDG];                  // per-edge alpha, then exp value
__device__ float    g_wv[9 * 2 * DIN];             // W[r] @ a_{src,dst}[r]

// ---------------- helpers ----------------
__device__ __forceinline__ float dot4(float4 a, float4 b) {
    return a.x*b.x + a.y*b.y + a.z*b.z + a.w*b.w;
}

__device__ __forceinline__ unsigned f2key(float f) {
    unsigned u = __float_as_uint(f);
    return (u & 0x80000000u) ? ~u : (u | 0x80000000u);
}
__device__ __forceinline__ float key2f(unsigned k) {
    return (k & 0x80000000u) ? __uint_as_float(k ^ 0x80000000u) : __uint_as_float(~k);
}

// ---------------- K0: init ----------------
__global__ void k_zero_out(float4* out, int n4) {
    int i = blockIdx.x * blockDim.x + threadIdx.x;
    if (i < n4) out[i] = make_float4(0.f, 0.f, 0.f, 0.f);
}
__global__ void k_init_md() {
    int i = blockIdx.x * blockDim.x + threadIdx.x;
    if (i < TOTROWS) { g_m[i] = 0u; g_den[i] = 0.f; }
}

// ---------------- K1: wv[r][role] = W[r] @ a_{role}[r] ----------------
__global__ void k_wv(const float* __restrict__ W, const float* __restrict__ as_,
                     const float* __restrict__ ad_) {
    int idx = blockIdx.x * blockDim.x + threadIdx.x;
    if (idx >= 9 * 2 * DIN) return;
    int k = idx & (DIN - 1);
    int rr = idx >> 9;         // (r*2 + role)
    int role = rr & 1;
    int r = rr >> 1;
    const float* a = (role ? ad_ : as_) + r * DOUT;
    const float* w = W + (size_t)r * DIN * DOUT + (size_t)k * DOUT;
    float s = 0.f;
    #pragma unroll 8
    for (int j = 0; j < DOUT; j++) s = fmaf(w[j], a[j], s);
    g_wv[r * 1024 + role * DIN + k] = s;
}

// ---------------- K2: per-node attention logit halves (6 matvec dots / node) ----------------
__device__ __forceinline__ float warp_dot512(float4 x0, float4 x1, float4 x2, float4 x3,
                                             const float* vecbase, int lane) {
    const float4* vv = (const float4*)vecbase;
    float s = dot4(x0, vv[lane]) + dot4(x1, vv[lane + 32])
            + dot4(x2, vv[lane + 64]) + dot4(x3, vv[lane + 96]);
    #pragma unroll
    for (int o = 16; o; o >>= 1) s += __shfl_xor_sync(0xffffffffu, s, o);
    return s;
}

__global__ void k_node_dots(const float* __restrict__ x, int n,
                            int r0, int r1, int r2, int so0, int so1, int so2,
                            int d0, int d1, int d2, int q0, int q1, int q2) {
    int gw   = (blockIdx.x * blockDim.x + threadIdx.x) >> 5;
    int lane = threadIdx.x & 31;
    if (gw >= n) return;
    const float4* xr = (const float4*)(x + (size_t)gw * DIN);
    float4 x0 = xr[lane], x1 = xr[lane + 32], x2 = xr[lane + 64], x3 = xr[lane + 96];
    float s;
    s = warp_dot512(x0, x1, x2, x3, g_wv + r0 * 1024,       lane); if (!lane) g_ssrc[so0 + gw] = s;
    s = warp_dot512(x0, x1, x2, x3, g_wv + r1 * 1024,       lane); if (!lane) g_ssrc[so1 + gw] = s;
    s = warp_dot512(x0, x1, x2, x3, g_wv + r2 * 1024,       lane); if (!lane) g_ssrc[so2 + gw] = s;
    s = warp_dot512(x0, x1, x2, x3, g_wv + d0 * 1024 + DIN, lane); if (!lane) g_sdst[q0 + gw] = s;
    s = warp_dot512(x0, x1, x2, x3, g_wv + d1 * 1024 + DIN, lane); if (!lane) g_sdst[q1 + gw] = s;
    s = warp_dot512(x0, x1, x2, x3, g_wv + d2 * 1024 + DIN, lane); if (!lane) g_sdst[q2 + gw] = s;
}

// ---------------- K3: SGEMM  H[soff..] = A(Mx512) @ W(512x128) ----------------
// 128x128 block tile, BK=8, 8x8 per thread, 256 threads, global->reg prefetch.
__global__ __launch_bounds__(256, 2)
void k_sgemm(const float* __restrict__ A, const float* __restrict__ W, int M, int hoff) {
    __shared__ float As[8][132];   // padded: conflict-free transposed stores, 16B-aligned rows
    __shared__ float Bs[8][128];

    float* C = g_H + (size_t)hoff * DOUT;
    int tid  = threadIdx.x;
    int brow = blockIdx.x * 128;

    int arow = tid >> 1;                 // 0..127
    int ac4  = (tid & 1) * 4;            // 0 or 4
    size_t aidx = (size_t)min(brow + arow, M - 1) * DIN + ac4;

    int bro = tid >> 5;                  // 0..7  (k-row within B tile)
    int bc4 = (tid & 31) * 4;            // 0..124

    int trow = (tid >> 4) * 8;
    int tcol = (tid & 15) * 8;

    float acc[8][8];
    #pragma unroll
    for (int i = 0; i < 8; i++)
        #pragma unroll
        for (int j = 0; j < 8; j++) acc[i][j] = 0.f;

    float4 pa = *(const float4*)(A + aidx);
    float4 pb = *(const float4*)(W + (size_t)bro * DOUT + bc4);

    for (int kt = 0; kt < DIN / 8; kt++) {
        __syncthreads();
        As[ac4 + 0][arow] = pa.x;
        As[ac4 + 1][arow] = pa.y;
        As[ac4 + 2][arow] = pa.z;
        As[ac4 + 3][arow] = pa.w;
        *(float4*)&Bs[bro][bc4] = pb;
        __syncthreads();

        if (kt < DIN / 8 - 1) {
            pa = *(const float4*)(A + aidx + (size_t)(kt + 1) * 8);
            pb = *(const float4*)(W + (size_t)((kt + 1) * 8 + bro) * DOUT + bc4);
        }

        #pragma unroll
        for (int k = 0; k < 8; k++) {
            float4 a0 = *(const float4*)&As[k][trow];
            float4 a1 = *(const float4*)&As[k][trow + 4];
            float4 b0 = *(const float4*)&Bs[k][tcol];
            float4 b1 = *(const float4*)&Bs[k][tcol + 4];
            float av[8] = {a0.x, a0.y, a0.z, a0.w, a1.x, a1.y, a1.z, a1.w};
            float bv[8] = {b0.x, b0.y, b0.z, b0.w, b1.x, b1.y, b1.z, b1.w};
            #pragma unroll
            for (int i = 0; i < 8; i++)
                #pragma unroll
                for (int j = 0; j < 8; j++)
                    acc[i][j] = fmaf(av[i], bv[j], acc[i][j]);
        }
    }

    #pragma unroll
    for (int i = 0; i < 8; i++) {
        int r = brow + trow + i;
        if (r < M) {
            *(float4*)&C[(size_t)r * DOUT + tcol]     = make_float4(acc[i][0], acc[i][1], acc[i][2], acc[i][3]);
            *(float4*)&C[(size_t)r * DOUT + tcol + 4] = make_float4(acc[i][4], acc[i][5], acc[i][6], acc[i][7]);
        }
    }
}

// ---------------- K4: per-edge logit + segment max ----------------
__global__ void k_edge_alpha(const int* __restrict__ ei, int soff, int doff, int eoff) {
    int e = blockIdx.x * blockDim.x + threadIdx.x;
    if (e >= EDG) return;
    int s = ei[e], d = ei[EDG + e];
    float a = g_ssrc[soff + s] + g_sdst[doff + d];
    a = (a > 0.f) ? a : 0.2f * a;          // leaky_relu(0.2)
    g_e[eoff + e] = a;
    atomicMax(&g_m[doff + d], f2key(a));
}

// ---------------- K5: per-edge exp + segment sum ----------------
__global__ void k_edge_exp(const int* __restrict__ ei, int doff, int eoff) {
    int e = blockIdx.x * blockDim.x + threadIdx.x;
    if (e >= EDG) return;
    int d = ei[EDG + e];
    float m = key2f(g_m[doff + d]);
    float v = __expf(g_e[eoff + e] - m);
    g_e[eoff + e] = v;
    atomicAdd(&g_den[doff + d], v);
}

// ---------------- K6: weighted scatter of h_src into output accumulator ----------------
__global__ void k_edge_scatter(const int* __restrict__ ei, int hoff, int doff, int eoff,
                               float* __restrict__ out) {
    int t = blockIdx.x * blockDim.x + threadIdx.x;
    int w = t >> 5, lane = t & 31;
    if (w >= EDG) return;
    int s = ei[w], d = ei[EDG + w];
    float wt = g_e[eoff + w] / g_den[doff + d];
    const float4* h = (const float4*)(g_H + (size_t)(hoff + s) * DOUT);
    float4 v = h[lane];
    float* p = out + (size_t)d * DOUT + lane * 4;
    asm volatile("red.global.add.v4.f32 [%0], {%1,%2,%3,%4};"
                 :: "l"(p), "f"(v.x * wt), "f"(v.y * wt), "f"(v.z * wt), "f"(v.w * wt)
                 : "memory");
}

// ---------------- K7: mean over 3 relations, + bias, relu ----------------
__global__ void k_finalize(float* out, const float* __restrict__ bias,
                           int ra, int rb, int rc, int nelem) {
    int idx = blockIdx.x * blockDim.x + threadIdx.x;
    if (idx >= nelem) return;
    int j = idx & (DOUT - 1);
    float b = bias[ra * DOUT + j] + bias[rb * DOUT + j] + bias[rc * DOUT + j];
    float v = (out[idx] + b) * (1.0f / 3.0f);
    out[idx] = (v > 0.f) ? v : 0.f;
}

// ---------------- launch ----------------
extern "C" void kernel_launch(void* const* d_in, const int* in_sizes, int n_in,
                              void* d_out, int out_size) {
    const float* X[3] = {(const float*)d_in[0], (const float*)d_in[1], (const float*)d_in[2]};
    const int* EI[9];
    for (int r = 0; r < 9; r++) EI[r] = (const int*)d_in[3 + r];
    const float* W    = (const float*)d_in[12];
    const float* as_  = (const float*)d_in[13];
    const float* ad_  = (const float*)d_in[14];
    const float* bias = (const float*)d_in[15];
    float* out = (float*)d_out;

    // init
    int n4 = out_size / 4;
    k_zero_out<<<(n4 + 255) / 256, 256>>>((float4*)out, n4);
    k_init_md<<<(TOTROWS + 255) / 256, 256>>>();

    // attention-vector matvec precompute + per-node logit halves
    k_wv<<<(9 * 2 * DIN + 255) / 256, 256>>>(W, as_, ad_);
    k_node_dots<<<(NP * 32 + 255) / 256, 256>>>(X[0], NP, 0, 1, 2, 0, 100000, 200000,
                                                0, 4, 7, 0, 310000, 510000);
    k_node_dots<<<(NL * 32 + 255) / 256, 256>>>(X[1], NL, 3, 4, 5, 300000, 380000, 460000,
                                                1, 3, 8, 100000, 230000, 610000);
    k_node_dots<<<(NG * 32 + 255) / 256, 256>>>(X[2], NG, 6, 7, 8, 540000, 590000, 640000,
                                                2, 5, 6, 180000, 410000, 460000);

    // projections H[r] = X[src(r)] @ W[r]
    for (int r = 0; r < 9; r++) {
        int M = NTY[SRC_T[r]];
        k_sgemm<<<(M + 127) / 128, 256>>>(X[SRC_T[r]], W + (size_t)r * DIN * DOUT, M, SOFF[r]);
    }

    // edge softmax (3 passes)
    for (int r = 0; r < 9; r++)
        k_edge_alpha<<<(EDG + 255) / 256, 256>>>(EI[r], SOFF[r], DOFF[r], r * EDG);
    for (int r = 0; r < 9; r++)
        k_edge_exp<<<(EDG + 255) / 256, 256>>>(EI[r], DOFF[r], r * EDG);
    for (int r = 0; r < 9; r++) {
        float* ob = out + (size_t)OUTROW[DST_T[r]] * DOUT;
        k_edge_scatter<<<(EDG * 32 + 255) / 256, 256>>>(EI[r], SOFF[r], DOFF[r], r * EDG, ob);
    }

    // mean + bias + relu
    k_finalize<<<(NP * DOUT + 255) / 256, 256>>>(out, bias, 0, 4, 7, NP * DOUT);
    k_finalize<<<(NL * DOUT + 255) / 256, 256>>>(out + (size_t)NP * DOUT, bias, 1, 3, 8, NL * DOUT);
    k_finalize<<<(NG * DOUT + 255) / 256, 256>>>(out + (size_t)(NP + NL) * DOUT, bias, 2, 5, 6, NG * DOUT);
}

// round 4
// speedup vs baseline: 1.5831x; 1.5831x over previous
#include <cuda_runtime.h>
#include <cuda_bf16.h>
#include <cstdint>

// ---------------- problem constants ----------------
#define NP 100000
#define NL 80000
#define NG 50000
#define EDG 400000
#define DIN 512
#define DOUT 128
#define TOTROWS 690000
#define XROWS 230000          // NP+NL+NG

// per-relation metadata (host side)
static const int SRC_T[9] = {0,0,0,1,1,1,2,2,2};
static const int DST_T[9] = {0,1,2,1,0,2,2,0,1};
static const int NTY[3]   = {NP, NL, NG};
static const int SOFF[9]  = {0,100000,200000,300000,380000,460000,540000,590000,640000};
static const int DOFF[9]  = {0,100000,180000,230000,310000,410000,460000,510000,610000};
static const int OUTROW[3]= {0, NP, NP+NL};
static const int XOFF[3]  = {0, NP, NP+NL};

// ---------------- device scratch (static, no allocation) ----------------
__device__ float          g_H[(size_t)TOTROWS * DOUT];
__device__ __nv_bfloat16  g_Xh[(size_t)XROWS * DIN];
__device__ __nv_bfloat16  g_Xl[(size_t)XROWS * DIN];
__device__ __nv_bfloat16  g_Wh[9 * DOUT * DIN];   // [r][n][k]
__device__ __nv_bfloat16  g_Wl[9 * DOUT * DIN];
__device__ float    g_ssrc[TOTROWS];
__device__ float    g_sdst[TOTROWS];
__device__ unsigned g_m[TOTROWS];
__device__ float    g_den[TOTROWS];
__device__ float    g_e[9 * EDG];
__device__ float    g_wv[9 * 2 * DIN];

// ---------------- small helpers ----------------
__device__ __forceinline__ float dot4(float4 a, float4 b) {
    return a.x*b.x + a.y*b.y + a.z*b.z + a.w*b.w;
}
__device__ __forceinline__ unsigned f2key(float f) {
    unsigned u = __float_as_uint(f);
    return (u & 0x80000000u) ? ~u : (u | 0x80000000u);
}
__device__ __forceinline__ float key2f(unsigned k) {
    return (k & 0x80000000u) ? __uint_as_float(k ^ 0x80000000u) : __uint_as_float(~k);
}
__device__ __forceinline__ uint32_t smem_u32(const void* p) {
    uint32_t a;
    asm("{ .reg .u64 t; cvta.to.shared.u64 t, %1; cvt.u32.u64 %0, t; }" : "=r"(a) : "l"(p));
    return a;
}
__device__ __forceinline__ void cp_async16(uint32_t sdst, const void* gsrc) {
    asm volatile("cp.async.cg.shared.global [%0], [%1], 16;" :: "r"(sdst), "l"(gsrc) : "memory");
}
__device__ __forceinline__ void ldm_x4(uint32_t* r, uint32_t addr) {
    asm volatile("ldmatrix.sync.aligned.m8n8.x4.shared.b16 {%0,%1,%2,%3}, [%4];"
                 : "=r"(r[0]), "=r"(r[1]), "=r"(r[2]), "=r"(r[3]) : "r"(addr));
}
__device__ __forceinline__ void mma16816(float* d, const uint32_t* a, const uint32_t* b) {
    asm volatile("mma.sync.aligned.m16n8k16.row.col.f32.bf16.bf16.f32 "
                 "{%0,%1,%2,%3},{%4,%5,%6,%7},{%8,%9},{%0,%1,%2,%3};"
                 : "+f"(d[0]), "+f"(d[1]), "+f"(d[2]), "+f"(d[3])
                 : "r"(a[0]), "r"(a[1]), "r"(a[2]), "r"(a[3]), "r"(b[0]), "r"(b[1]));
}

// ---------------- K0: init ----------------
__global__ void k_zero_out(float4* out, int n4) {
    int i = blockIdx.x * blockDim.x + threadIdx.x;
    if (i < n4) out[i] = make_float4(0.f, 0.f, 0.f, 0.f);
}
__global__ void k_init_md() {
    int i = blockIdx.x * blockDim.x + threadIdx.x;
    if (i < TOTROWS) { g_m[i] = 0u; g_den[i] = 0.f; }
}

// ---------------- K1: convert X -> bf16 hi/lo ----------------
__global__ void k_cvt_x(const float4* __restrict__ x, int n4, long long off4) {
    int i = blockIdx.x * blockDim.x + threadIdx.x;
    if (i >= n4) return;
    float4 v = x[i];
    __nv_bfloat16 h0 = __float2bfloat16(v.x);
    __nv_bfloat16 h1 = __float2bfloat16(v.y);
    __nv_bfloat16 h2 = __float2bfloat16(v.z);
    __nv_bfloat16 h3 = __float2bfloat16(v.w);
    __nv_bfloat16 l0 = __float2bfloat16(v.x - __bfloat162float(h0));
    __nv_bfloat16 l1 = __float2bfloat16(v.y - __bfloat162float(h1));
    __nv_bfloat16 l2 = __float2bfloat16(v.z - __bfloat162float(h2));
    __nv_bfloat16 l3 = __float2bfloat16(v.w - __bfloat162float(h3));
    size_t base = (size_t)(off4 + i) * 4;
    __nv_bfloat162* ph = (__nv_bfloat162*)(g_Xh + base);
    __nv_bfloat162* pl = (__nv_bfloat162*)(g_Xl + base);
    ph[0] = __nv_bfloat162(h0, h1); ph[1] = __nv_bfloat162(h2, h3);
    pl[0] = __nv_bfloat162(l0, l1); pl[1] = __nv_bfloat162(l2, l3);
}

// ---------------- K1b: W -> transposed bf16 hi/lo  B[r][n][k] = W[r][k][n] ----------------
__global__ void k_cvt_w(const float* __restrict__ W) {
    int idx = blockIdx.x * blockDim.x + threadIdx.x;
    if (idx >= 9 * DIN * DOUT) return;
    int r = idx >> 16;
    int k = (idx >> 7) & 511;
    int n = idx & 127;
    float w = W[idx];
    __nv_bfloat16 h = __float2bfloat16(w);
    __nv_bfloat16 l = __float2bfloat16(w - __bfloat162float(h));
    int o = (r << 16) + n * DIN + k;
    g_Wh[o] = h; g_Wl[o] = l;
}

// ---------------- K2: wv[r][role] = W[r] @ a ----------------
__global__ void k_wv(const float* __restrict__ W, const float* __restrict__ as_,
                     const float* __restrict__ ad_) {
    int idx = blockIdx.x * blockDim.x + threadIdx.x;
    if (idx >= 9 * 2 * DIN) return;
    int k = idx & (DIN - 1);
    int rr = idx >> 9;
    int role = rr & 1;
    int r = rr >> 1;
    const float* a = (role ? ad_ : as_) + r * DOUT;
    const float* w = W + (size_t)r * DIN * DOUT + (size_t)k * DOUT;
    float s = 0.f;
    #pragma unroll 8
    for (int j = 0; j < DOUT; j++) s = fmaf(w[j], a[j], s);
    g_wv[r * 1024 + role * DIN + k] = s;
}

// ---------------- K3: per-node attention logit halves ----------------
__device__ __forceinline__ float warp_dot512(float4 x0, float4 x1, float4 x2, float4 x3,
                                             const float* vecbase, int lane) {
    const float4* vv = (const float4*)vecbase;
    float s = dot4(x0, vv[lane]) + dot4(x1, vv[lane + 32])
            + dot4(x2, vv[lane + 64]) + dot4(x3, vv[lane + 96]);
    #pragma unroll
    for (int o = 16; o; o >>= 1) s += __shfl_xor_sync(0xffffffffu, s, o);
    return s;
}
__global__ void k_node_dots(const float* __restrict__ x, int n,
                            int r0, int r1, int r2, int so0, int so1, int so2,
                            int d0, int d1, int d2, int q0, int q1, int q2) {
    int gw   = (blockIdx.x * blockDim.x + threadIdx.x) >> 5;
    int lane = threadIdx.x & 31;
    if (gw >= n) return;
    const float4* xr = (const float4*)(x + (size_t)gw * DIN);
    float4 x0 = xr[lane], x1 = xr[lane + 32], x2 = xr[lane + 64], x3 = xr[lane + 96];
    float s;
    s = warp_dot512(x0, x1, x2, x3, g_wv + r0 * 1024,       lane); if (!lane) g_ssrc[so0 + gw] = s;
    s = warp_dot512(x0, x1, x2, x3, g_wv + r1 * 1024,       lane); if (!lane) g_ssrc[so1 + gw] = s;
    s = warp_dot512(x0, x1, x2, x3, g_wv + r2 * 1024,       lane); if (!lane) g_ssrc[so2 + gw] = s;
    s = warp_dot512(x0, x1, x2, x3, g_wv + d0 * 1024 + DIN, lane); if (!lane) g_sdst[q0 + gw] = s;
    s = warp_dot512(x0, x1, x2, x3, g_wv + d1 * 1024 + DIN, lane); if (!lane) g_sdst[q1 + gw] = s;
    s = warp_dot512(x0, x1, x2, x3, g_wv + d2 * 1024 + DIN, lane); if (!lane) g_sdst[q2 + gw] = s;
}

// ---------------- K4: split-bf16 mma.sync GEMM  H = X @ W ----------------
// CTA tile 128x128, BK=32, 2-stage cp.async double buffer.
// smem per stage: Ah,Al,Bh,Bl each 128 rows x 80B (32 bf16 + 8 pad) = 10240B -> 40960B.
#define GST   40960
#define GROWB 80
#define GE_SMEM (2 * GST)

__global__ __launch_bounds__(256, 2)
void k_mma_gemm(int rowoff, int M, int rel, int hoff) {
    extern __shared__ __align__(128) char smem[];
    uint32_t sb = smem_u32(smem);
    int tid  = threadIdx.x;
    int lane = tid & 31;
    int warp = tid >> 5;
    int wm = warp & 1;          // 0..1  (M band of 64)
    int wn = warp >> 1;         // 0..3  (N band of 32)
    int tile0 = blockIdx.x * 128;

    const __nv_bfloat16* baseA[2] = { g_Xh + (size_t)rowoff * DIN, g_Xl + (size_t)rowoff * DIN };
    const __nv_bfloat16* baseB[2] = { g_Wh + ((size_t)rel << 16), g_Wl + ((size_t)rel << 16) };

    float acc[4][4][4];
    #pragma unroll
    for (int i = 0; i < 4; i++)
        #pragma unroll
        for (int j = 0; j < 4; j++)
            #pragma unroll
            for (int q = 0; q < 4; q++) acc[i][j][q] = 0.f;

    // loader: 2048 16B chunks per stage, 8 per thread
    auto load_chunk = [&](int c) {
        uint32_t stb = sb + (c & 1) * GST;
        int kbase = c * 32;
        #pragma unroll
        for (int t = 0; t < 8; t++) {
            int id  = tid + t * 256;
            int buf = id >> 9;            // 0=Ah 1=Al 2=Bh 3=Bl
            int rem = id & 511;
            int row = rem >> 2;
            int c16 = rem & 3;
            const __nv_bfloat16* g;
            if (buf < 2) {
                int grow = tile0 + row; if (grow >= M) grow = M - 1;
                g = baseA[buf] + (size_t)grow * DIN;
            } else {
                g = baseB[buf - 2] + (size_t)row * DIN;
            }
            g += kbase + c16 * 8;
            cp_async16(stb + buf * 10240 + row * GROWB + c16 * 16, g);
        }
        asm volatile("cp.async.commit_group;" ::: "memory");
    };

    // per-thread ldmatrix address components
    uint32_t a_off = (uint32_t)(wm * 64 + (lane & 15)) * GROWB + (lane & 16);
    uint32_t b_off = (uint32_t)(wn * 32 + (lane & 7) + ((lane & 16) ? 8 : 0)) * GROWB
                   + ((lane & 8) << 1);

    load_chunk(0);

    for (int c = 0; c < 16; c++) {
        if (c < 15) {
            load_chunk(c + 1);
            asm volatile("cp.async.wait_group 1;" ::: "memory");
        } else {
            asm volatile("cp.async.wait_group 0;" ::: "memory");
        }
        __syncthreads();

        uint32_t stb = sb + (c & 1) * GST;
        uint32_t ah_s = stb;
        uint32_t al_s = stb + 10240;
        uint32_t bh_s = stb + 20480;
        uint32_t bl_s = stb + 30720;

        #pragma unroll
        for (int ks = 0; ks < 2; ks++) {
            uint32_t kb = ks * 32;
            uint32_t AH[4][4], AL[4][4], B[2][4];
            #pragma unroll
            for (int mf = 0; mf < 4; mf++) {
                ldm_x4(AH[mf], ah_s + a_off + mf * (16 * GROWB) + kb);
                ldm_x4(AL[mf], al_s + a_off + mf * (16 * GROWB) + kb);
            }
            // p0: Ah*Bh  and  p2: Al*Bh
            #pragma unroll
            for (int g = 0; g < 2; g++)
                ldm_x4(B[g], bh_s + b_off + g * (16 * GROWB) + kb);
            #pragma unroll
            for (int mf = 0; mf < 4; mf++)
                #pragma unroll
                for (int nf = 0; nf < 4; nf++) {
                    const uint32_t* bp = &B[nf >> 1][(nf & 1) * 2];
                    mma16816(acc[mf][nf], AH[mf], bp);
                    mma16816(acc[mf][nf], AL[mf], bp);
                }
            // p1: Ah*Bl
            #pragma unroll
            for (int g = 0; g < 2; g++)
                ldm_x4(B[g], bl_s + b_off + g * (16 * GROWB) + kb);
            #pragma unroll
            for (int mf = 0; mf < 4; mf++)
                #pragma unroll
                for (int nf = 0; nf < 4; nf++)
                    mma16816(acc[mf][nf], AH[mf], &B[nf >> 1][(nf & 1) * 2]);
        }
        __syncthreads();
    }

    // epilogue: acc -> g_H
    float* Cb = g_H + (size_t)hoff * DOUT;
    int r_base = tile0 + wm * 64 + (lane >> 2);
    int c_base = wn * 32 + (lane & 3) * 2;
    #pragma unroll
    for (int mf = 0; mf < 4; mf++) {
        #pragma unroll
        for (int nf = 0; nf < 4; nf++) {
            int r = r_base + mf * 16;
            int cc = c_base + nf * 8;
            if (r < M)
                *(float2*)(Cb + (size_t)r * DOUT + cc)       = make_float2(acc[mf][nf][0], acc[mf][nf][1]);
            if (r + 8 < M)
                *(float2*)(Cb + (size_t)(r + 8) * DOUT + cc) = make_float2(acc[mf][nf][2], acc[mf][nf][3]);
        }
    }
}

// ---------------- K5: per-edge logit + segment max ----------------
__global__ void k_edge_alpha(const int* __restrict__ ei, int soff, int doff, int eoff) {
    int e = blockIdx.x * blockDim.x + threadIdx.x;
    if (e >= EDG) return;
    int s = ei[e], d = ei[EDG + e];
    float a = g_ssrc[soff + s] + g_sdst[doff + d];
    a = (a > 0.f) ? a : 0.2f * a;
    g_e[eoff + e] = a;
    atomicMax(&g_m[doff + d], f2key(a));
}

// ---------------- K6: per-edge exp + segment sum ----------------
__global__ void k_edge_exp(const int* __restrict__ ei, int doff, int eoff) {
    int e = blockIdx.x * blockDim.x + threadIdx.x;
    if (e >= EDG) return;
    int d = ei[EDG + e];
    float m = key2f(g_m[doff + d]);
    float v = __expf(g_e[eoff + e] - m);
    g_e[eoff + e] = v;
    atomicAdd(&g_den[doff + d], v);
}

// ---------------- K7: weighted scatter ----------------
__global__ void k_edge_scatter(const int* __restrict__ ei, int hoff, int doff, int eoff,
                               float* __restrict__ out) {
    int t = blockIdx.x * blockDim.x + threadIdx.x;
    int w = t >> 5, lane = t & 31;
    if (w >= EDG) return;
    int s = ei[w], d = ei[EDG + w];
    float wt = g_e[eoff + w] / g_den[doff + d];
    const float4* h = (const float4*)(g_H + (size_t)(hoff + s) * DOUT);
    float4 v = h[lane];
    float* p = out + (size_t)d * DOUT + lane * 4;
    asm volatile("red.global.add.v4.f32 [%0], {%1,%2,%3,%4};"
                 :: "l"(p), "f"(v.x * wt), "f"(v.y * wt), "f"(v.z * wt), "f"(v.w * wt)
                 : "memory");
}

// ---------------- K8: mean + bias + relu ----------------
__global__ void k_finalize(float* out, const float* __restrict__ bias,
                           int ra, int rb, int rc, int nelem) {
    int idx = blockIdx.x * blockDim.x + threadIdx.x;
    if (idx >= nelem) return;
    int j = idx & (DOUT - 1);
    float b = bias[ra * DOUT + j] + bias[rb * DOUT + j] + bias[rc * DOUT + j];
    float v = (out[idx] + b) * (1.0f / 3.0f);
    out[idx] = (v > 0.f) ? v : 0.f;
}

// ---------------- launch ----------------
extern "C" void kernel_launch(void* const* d_in, const int* in_sizes, int n_in,
                              void* d_out, int out_size) {
    const float* X[3] = {(const float*)d_in[0], (const float*)d_in[1], (const float*)d_in[2]};
    const int* EI[9];
    for (int r = 0; r < 9; r++) EI[r] = (const int*)d_in[3 + r];
    const float* W    = (const float*)d_in[12];
    const float* as_  = (const float*)d_in[13];
    const float* ad_  = (const float*)d_in[14];
    const float* bias = (const float*)d_in[15];
    float* out = (float*)d_out;

    static int smem_set = 0;
    if (!smem_set) {
        cudaFuncSetAttribute(k_mma_gemm, cudaFuncAttributeMaxDynamicSharedMemorySize, GE_SMEM);
        smem_set = 1;
    }

    // init
    int n4 = out_size / 4;
    k_zero_out<<<(n4 + 255) / 256, 256>>>((float4*)out, n4);
    k_init_md<<<(TOTROWS + 255) / 256, 256>>>();

    // conversions
    k_cvt_x<<<(NP * 128 + 255) / 256, 256>>>((const float4*)X[0], NP * 128, (long long)XOFF[0] * 128);
    k_cvt_x<<<(NL * 128 + 255) / 256, 256>>>((const float4*)X[1], NL * 128, (long long)XOFF[1] * 128);
    k_cvt_x<<<(NG * 128 + 255) / 256, 256>>>((const float4*)X[2], NG * 128, (long long)XOFF[2] * 128);
    k_cvt_w<<<(9 * DIN * DOUT + 255) / 256, 256>>>(W);

    // attention-vector precompute + per-node logit halves
    k_wv<<<(9 * 2 * DIN + 255) / 256, 256>>>(W, as_, ad_);
    k_node_dots<<<(NP * 32 + 255) / 256, 256>>>(X[0], NP, 0, 1, 2, 0, 100000, 200000,
                                                0, 4, 7, 0, 310000, 510000);
    k_node_dots<<<(NL * 32 + 255) / 256, 256>>>(X[1], NL, 3, 4, 5, 300000, 380000, 460000,
                                                1, 3, 8, 100000, 230000, 610000);
    k_node_dots<<<(NG * 32 + 255) / 256, 256>>>(X[2], NG, 6, 7, 8, 540000, 590000, 640000,
                                                2, 5, 6, 180000, 410000, 460000);

    // tensor-core projections H[r] = X[src(r)] @ W[r]
    for (int r = 0; r < 9; r++) {
        int M = NTY[SRC_T[r]];
        k_mma_gemm<<<(M + 127) / 128, 256, GE_SMEM>>>(XOFF[SRC_T[r]], M, r, SOFF[r]);
    }

    // edge softmax (3 passes)
    for (int r = 0; r < 9; r++)
        k_edge_alpha<<<(EDG + 255) / 256, 256>>>(EI[r], SOFF[r], DOFF[r], r * EDG);
    for (int r = 0; r < 9; r++)
        k_edge_exp<<<(EDG + 255) / 256, 256>>>(EI[r], DOFF[r], r * EDG);
    for (int r = 0; r < 9; r++) {
        float* ob = out + (size_t)OUTROW[DST_T[r]] * DOUT;
        k_edge_scatter<<<(EDG * 32 + 255) / 256, 256>>>(EI[r], SOFF[r], DOFF[r], r * EDG, ob);
    }

    // mean + bias + relu
    k_finalize<<<(NP * DOUT + 255) / 256, 256>>>(out, bias, 0, 4, 7, NP * DOUT);
    k_finalize<<<(NL * DOUT + 255) / 256, 256>>>(out + (size_t)NP * DOUT, bias, 1, 3, 8, NL * DOUT);
    k_finalize<<<(NG * DOUT + 255) / 256, 256>>>(out + (size_t)(NP + NL) * DOUT, bias, 2, 5, 6, NG * DOUT);
}